// round 5
// baseline (speedup 1.0000x reference)
#include <cuda_runtime.h>
#include <cuda_bf16.h>
#include <math.h>
#include <stdint.h>

#define NN 100000
#define EE 1600000
#define D  128
#define HEADS 4
#define CH 32
#define NEG_SLOPE 0.2f
#define CAP 64                 // deg ~ Poisson(16); P(deg>64) ~ 2e-22 per node
#define PP_BLOCKS 148          // one wave on B300/GB300 (148/152 SMs)
#define PP_THREADS 256
#define NODES_PER_T 3          // 148*256*3 = 113664 >= NN

// ---------------- scratch ------------------------------------------------------
__device__ float g_bufA[NN * D];
__device__ float g_bufB[NN * D];
__device__ float g_xr[NN * D];
__device__ float g_ss[NN * HEADS];
__device__ float g_sd[NN * HEADS];
__device__ int   g_deg[NN];
__device__ int   g_offs[NN + 1];
__device__ int   g_cursor[NN];
__device__ int   g_sorted_src[EE];
__device__ int   g_bsum[PP_BLOCKS];
// grid barrier state (gen is monotonic across replays; count self-resets)
__device__ unsigned g_bar_count = 0;
__device__ volatile unsigned g_bar_gen = 0;

// ---------------- grid barrier (single-wave guaranteed: 148 blocks) -------------
__device__ __forceinline__ void gbar() {
    __syncthreads();
    if (threadIdx.x == 0) {
        __threadfence();
        unsigned gen = g_bar_gen;
        if (atomicAdd(&g_bar_count, 1u) == PP_BLOCKS - 1) {
            g_bar_count = 0;
            __threadfence();
            g_bar_gen = gen + 1;
        } else {
            while (g_bar_gen == gen) { }
        }
        __threadfence();
    }
    __syncthreads();
}

// ---------------- fused preprocessing: zero + count + scan + scatter ------------
__global__ void __launch_bounds__(PP_THREADS) preproc_kernel(const void* __restrict__ ei) {
    __shared__ int sm[PP_THREADS];
    __shared__ int s64s;
    __shared__ int blockpre;

    const int tid = threadIdx.x;
    const int b   = blockIdx.x;
    const int gt  = b * PP_THREADS + tid;
    const int gsize = PP_BLOCKS * PP_THREADS;

    // edge dtype detect: int64 => odd 32-bit words (high halves) all zero
    if (tid == 0) s64s = 1;
    __syncthreads();
    if (tid < 256)
        if (((const unsigned int*)ei)[2 * tid + 1] != 0u) s64s = 0;
    __syncthreads();
    const int s64 = s64s;

    // phase 0: zero degree counters
    for (int i = gt; i < NN; i += gsize) g_deg[i] = 0;
    gbar();

    // phase 1: count destinations
    if (s64) {
        const long long* e64 = (const long long*)ei;
        for (int i = gt; i < EE; i += gsize)
            atomicAdd(&g_deg[(int)e64[(long long)EE + i]], 1);
    } else {
        const int* e32 = (const int*)ei;
        for (int i = gt; i < EE; i += gsize)
            atomicAdd(&g_deg[e32[EE + i]], 1);
    }
    gbar();

    // phase 2a: per-thread partial sums over NODES_PER_T contiguous nodes,
    //           block scan, publish block total
    int v[NODES_PER_T];
    int node0 = gt * NODES_PER_T;
#pragma unroll
    for (int j = 0; j < NODES_PER_T; ++j) {
        int idx = node0 + j;
        v[j] = (idx < NN) ? g_deg[idx] : 0;
    }
    int tsum = 0;
#pragma unroll
    for (int j = 0; j < NODES_PER_T; ++j) tsum += v[j];
    sm[tid] = tsum;
    __syncthreads();
    for (int off = 1; off < PP_THREADS; off <<= 1) {
        int x = (tid >= off) ? sm[tid - off] : 0;
        __syncthreads();
        sm[tid] += x;
        __syncthreads();
    }
    int thread_pre = (tid == 0) ? 0 : sm[tid - 1];   // exclusive within block
    if (tid == PP_THREADS - 1) g_bsum[b] = sm[tid];
    gbar();

    // phase 2b: each block computes its own prefix over g_bsum[0..b)
    if (tid == 0) {
        int p = 0;
        for (int i = 0; i < b; ++i) p += g_bsum[i];
        blockpre = p;
    }
    __syncthreads();
    int run = blockpre + thread_pre;
#pragma unroll
    for (int j = 0; j < NODES_PER_T; ++j) {
        int idx = node0 + j;
        if (idx < NN) {
            g_offs[idx]   = run;
            g_cursor[idx] = run;
            run += v[j];
        }
    }
    if (gt == 0) g_offs[NN] = EE;
    gbar();

    // phase 3: scatter sources bucketed by destination
    if (s64) {
        const long long* e64 = (const long long*)ei;
        for (int i = gt; i < EE; i += gsize) {
            int s = (int)e64[i];
            int d = (int)e64[(long long)EE + i];
            int pos = atomicAdd(&g_cursor[d], 1);
            g_sorted_src[pos] = s;
        }
    } else {
        const int* e32 = (const int*)ei;
        for (int i = gt; i < EE; i += gsize) {
            int s = e32[i];
            int d = e32[EE + i];
            int pos = atomicAdd(&g_cursor[d], 1);
            g_sorted_src[pos] = s;
        }
    }
}

// ---------------- tf32 tensor-core GEMMs ----------------------------------------
__device__ __forceinline__ float to_tf32(float x) {
    uint32_t u;
    asm("cvt.rna.tf32.f32 %0, %1;" : "=r"(u) : "f"(x));
    return __uint_as_float(u);
}

#define MMA_TF32(c, av, bv)                                                  \
    asm volatile(                                                            \
        "mma.sync.aligned.m16n8k8.row.col.f32.tf32.tf32.f32 "                \
        "{%0,%1,%2,%3},{%4,%5,%6,%7},{%8,%9},{%0,%1,%2,%3};"                 \
        : "+f"((c)[0]), "+f"((c)[1]), "+f"((c)[2]), "+f"((c)[3])             \
        : "r"((av)[0]), "r"((av)[1]), "r"((av)[2]), "r"((av)[3]),            \
          "r"((bv)[0]), "r"((bv)[1]))

// ---- single-output GEMM with fused scores (layer 2) ----------------------------
template<bool SCORES>
__global__ void __launch_bounds__(256) gemm_tc_kernel(
    const float* __restrict__ A, const float* __restrict__ W,
    const float* __restrict__ a_src, const float* __restrict__ a_dst,
    float* __restrict__ out, float* __restrict__ ssrc, float* __restrict__ sdst)
{
    __shared__ float AsT[32][132];
    __shared__ float Ws[32][132];

    const int tid  = threadIdx.x;
    const int warp = tid >> 5, lane = tid & 31;
    const int g = lane >> 2, t = lane & 3;
    const int wm = warp >> 2;
    const int wn = warp & 3;
    const int m0 = wm * 64, n0 = wn * 32;
    const int row0 = blockIdx.x * 128;

    float acc[4][4][4];
#pragma unroll
    for (int i = 0; i < 4; ++i)
#pragma unroll
        for (int j = 0; j < 4; ++j)
#pragma unroll
            for (int k = 0; k < 4; ++k) acc[i][j][k] = 0.f;

    for (int kc = 0; kc < D; kc += 32) {
#pragma unroll
        for (int it = 0; it < 4; ++it) {
            int idx = tid + it * 256;
            int r = idx >> 3, q = idx & 7;
            int row = row0 + r;
            float4 v = make_float4(0.f, 0.f, 0.f, 0.f);
            if (row < NN) v = *(const float4*)&A[(long long)row * D + kc + q * 4];
            AsT[q * 4 + 0][r] = to_tf32(v.x);
            AsT[q * 4 + 1][r] = to_tf32(v.y);
            AsT[q * 4 + 2][r] = to_tf32(v.z);
            AsT[q * 4 + 3][r] = to_tf32(v.w);
        }
#pragma unroll
        for (int it = 0; it < 4; ++it) {
            int idx = tid + it * 256;
            int kr = idx >> 5, c4 = idx & 31;
            float4 v = *(const float4*)&W[(kc + kr) * D + c4 * 4];
            Ws[kr][c4 * 4 + 0] = to_tf32(v.x);
            Ws[kr][c4 * 4 + 1] = to_tf32(v.y);
            Ws[kr][c4 * 4 + 2] = to_tf32(v.z);
            Ws[kr][c4 * 4 + 3] = to_tf32(v.w);
        }
        __syncthreads();
#pragma unroll
        for (int ks = 0; ks < 32; ks += 8) {
            uint32_t a[4][4], b[4][2];
#pragma unroll
            for (int mt = 0; mt < 4; ++mt) {
                int mr = m0 + mt * 16 + g;
                a[mt][0] = __float_as_uint(AsT[ks + t][mr]);
                a[mt][1] = __float_as_uint(AsT[ks + t][mr + 8]);
                a[mt][2] = __float_as_uint(AsT[ks + t + 4][mr]);
                a[mt][3] = __float_as_uint(AsT[ks + t + 4][mr + 8]);
            }
#pragma unroll
            for (int nt = 0; nt < 4; ++nt) {
                int nc = n0 + nt * 8 + g;
                b[nt][0] = __float_as_uint(Ws[ks + t][nc]);
                b[nt][1] = __float_as_uint(Ws[ks + t + 4][nc]);
            }
#pragma unroll
            for (int mt = 0; mt < 4; ++mt)
#pragma unroll
                for (int nt = 0; nt < 4; ++nt)
                    MMA_TF32(acc[mt][nt], a[mt], b[nt]);
        }
        __syncthreads();
    }

    float2 asv[4], adv[4];
    if (SCORES) {
#pragma unroll
        for (int nt = 0; nt < 4; ++nt) {
            int c = nt * 8 + 2 * t;
            asv[nt] = make_float2(a_src[wn * CH + c], a_src[wn * CH + c + 1]);
            adv[nt] = make_float2(a_dst[wn * CH + c], a_dst[wn * CH + c + 1]);
        }
    }
#pragma unroll
    for (int mt = 0; mt < 4; ++mt) {
        int r_lo = row0 + m0 + mt * 16 + g;
        int r_hi = r_lo + 8;
        float su_lo = 0.f, du_lo = 0.f, su_hi = 0.f, du_hi = 0.f;
#pragma unroll
        for (int nt = 0; nt < 4; ++nt) {
            int col = n0 + nt * 8 + 2 * t;
            if (r_lo < NN)
                *(float2*)&out[(long long)r_lo * D + col] =
                    make_float2(acc[mt][nt][0], acc[mt][nt][1]);
            if (r_hi < NN)
                *(float2*)&out[(long long)r_hi * D + col] =
                    make_float2(acc[mt][nt][2], acc[mt][nt][3]);
            if (SCORES) {
                su_lo += acc[mt][nt][0] * asv[nt].x + acc[mt][nt][1] * asv[nt].y;
                du_lo += acc[mt][nt][0] * adv[nt].x + acc[mt][nt][1] * adv[nt].y;
                su_hi += acc[mt][nt][2] * asv[nt].x + acc[mt][nt][3] * asv[nt].y;
                du_hi += acc[mt][nt][2] * adv[nt].x + acc[mt][nt][3] * adv[nt].y;
            }
        }
        if (SCORES) {
#pragma unroll
            for (int off = 1; off <= 2; off <<= 1) {
                su_lo += __shfl_xor_sync(0xffffffffu, su_lo, off);
                du_lo += __shfl_xor_sync(0xffffffffu, du_lo, off);
                su_hi += __shfl_xor_sync(0xffffffffu, su_hi, off);
                du_hi += __shfl_xor_sync(0xffffffffu, du_hi, off);
            }
            if (t == 0) {
                if (r_lo < NN) { ssrc[r_lo * HEADS + wn] = su_lo; sdst[r_lo * HEADS + wn] = du_lo; }
                if (r_hi < NN) { ssrc[r_hi * HEADS + wn] = su_hi; sdst[r_hi * HEADS + wn] = du_hi; }
            }
        }
    }
}

// ---- dual-output GEMM: [x@W1 | x@Wr] in one pass over x -------------------------
__global__ void __launch_bounds__(512) gemm_dual_kernel(
    const float* __restrict__ A,
    const float* __restrict__ W1, const float* __restrict__ Wr,
    const float* __restrict__ a_src, const float* __restrict__ a_dst,
    float* __restrict__ out1, float* __restrict__ outr,
    float* __restrict__ ssrc, float* __restrict__ sdst)
{
    __shared__ float AsT[32][132];
    __shared__ float Ws[32][260];

    const int tid  = threadIdx.x;
    const int warp = tid >> 5, lane = tid & 31;
    const int g = lane >> 2, t = lane & 3;
    const int wm = warp >> 3;
    const int wn = warp & 7;
    const int m0 = wm * 64, n0 = wn * 32;
    const int row0 = blockIdx.x * 128;

    float acc[4][4][4];
#pragma unroll
    for (int i = 0; i < 4; ++i)
#pragma unroll
        for (int j = 0; j < 4; ++j)
#pragma unroll
            for (int k = 0; k < 4; ++k) acc[i][j][k] = 0.f;

    for (int kc = 0; kc < D; kc += 32) {
#pragma unroll
        for (int it = 0; it < 2; ++it) {
            int idx = tid + it * 512;
            int r = idx >> 3, q = idx & 7;
            int row = row0 + r;
            float4 v = make_float4(0.f, 0.f, 0.f, 0.f);
            if (row < NN) v = *(const float4*)&A[(long long)row * D + kc + q * 4];
            AsT[q * 4 + 0][r] = to_tf32(v.x);
            AsT[q * 4 + 1][r] = to_tf32(v.y);
            AsT[q * 4 + 2][r] = to_tf32(v.z);
            AsT[q * 4 + 3][r] = to_tf32(v.w);
        }
#pragma unroll
        for (int it = 0; it < 4; ++it) {
            int idx = tid + it * 512;
            int kr = idx >> 6;
            int c4 = idx & 63;
            float4 v;
            if (c4 < 32) v = *(const float4*)&W1[(kc + kr) * D + c4 * 4];
            else         v = *(const float4*)&Wr[(kc + kr) * D + (c4 - 32) * 4];
            Ws[kr][c4 * 4 + 0] = to_tf32(v.x);
            Ws[kr][c4 * 4 + 1] = to_tf32(v.y);
            Ws[kr][c4 * 4 + 2] = to_tf32(v.z);
            Ws[kr][c4 * 4 + 3] = to_tf32(v.w);
        }
        __syncthreads();
#pragma unroll
        for (int ks = 0; ks < 32; ks += 8) {
            uint32_t a[4][4], b[4][2];
#pragma unroll
            for (int mt = 0; mt < 4; ++mt) {
                int mr = m0 + mt * 16 + g;
                a[mt][0] = __float_as_uint(AsT[ks + t][mr]);
                a[mt][1] = __float_as_uint(AsT[ks + t][mr + 8]);
                a[mt][2] = __float_as_uint(AsT[ks + t + 4][mr]);
                a[mt][3] = __float_as_uint(AsT[ks + t + 4][mr + 8]);
            }
#pragma unroll
            for (int nt = 0; nt < 4; ++nt) {
                int nc = n0 + nt * 8 + g;
                b[nt][0] = __float_as_uint(Ws[ks + t][nc]);
                b[nt][1] = __float_as_uint(Ws[ks + t + 4][nc]);
            }
#pragma unroll
            for (int mt = 0; mt < 4; ++mt)
#pragma unroll
                for (int nt = 0; nt < 4; ++nt)
                    MMA_TF32(acc[mt][nt], a[mt], b[nt]);
        }
        __syncthreads();
    }

    const bool is1 = (wn < 4);
    float* outp = is1 ? out1 : outr;
    const int cbase = is1 ? n0 : (n0 - 128);
    float2 asv[4], adv[4];
    if (is1) {
#pragma unroll
        for (int nt = 0; nt < 4; ++nt) {
            int c = nt * 8 + 2 * t;
            asv[nt] = make_float2(a_src[wn * CH + c], a_src[wn * CH + c + 1]);
            adv[nt] = make_float2(a_dst[wn * CH + c], a_dst[wn * CH + c + 1]);
        }
    }
#pragma unroll
    for (int mt = 0; mt < 4; ++mt) {
        int r_lo = row0 + m0 + mt * 16 + g;
        int r_hi = r_lo + 8;
        float su_lo = 0.f, du_lo = 0.f, su_hi = 0.f, du_hi = 0.f;
#pragma unroll
        for (int nt = 0; nt < 4; ++nt) {
            int col = cbase + nt * 8 + 2 * t;
            if (r_lo < NN)
                *(float2*)&outp[(long long)r_lo * D + col] =
                    make_float2(acc[mt][nt][0], acc[mt][nt][1]);
            if (r_hi < NN)
                *(float2*)&outp[(long long)r_hi * D + col] =
                    make_float2(acc[mt][nt][2], acc[mt][nt][3]);
            if (is1) {
                su_lo += acc[mt][nt][0] * asv[nt].x + acc[mt][nt][1] * asv[nt].y;
                du_lo += acc[mt][nt][0] * adv[nt].x + acc[mt][nt][1] * adv[nt].y;
                su_hi += acc[mt][nt][2] * asv[nt].x + acc[mt][nt][3] * asv[nt].y;
                du_hi += acc[mt][nt][2] * adv[nt].x + acc[mt][nt][3] * adv[nt].y;
            }
        }
        if (is1) {
#pragma unroll
            for (int off = 1; off <= 2; off <<= 1) {
                su_lo += __shfl_xor_sync(0xffffffffu, su_lo, off);
                du_lo += __shfl_xor_sync(0xffffffffu, du_lo, off);
                su_hi += __shfl_xor_sync(0xffffffffu, su_hi, off);
                du_hi += __shfl_xor_sync(0xffffffffu, du_hi, off);
            }
            if (t == 0) {
                if (r_lo < NN) { ssrc[r_lo * HEADS + wn] = su_lo; sdst[r_lo * HEADS + wn] = du_lo; }
                if (r_hi < NN) { ssrc[r_hi * HEADS + wn] = su_hi; sdst[r_hi * HEADS + wn] = du_hi; }
            }
        }
    }
}

// ---------------- softmax + aggregation (no max shift; packed (src,e) planes) ---
__device__ __forceinline__ float lrelu(float v) { return v > 0.f ? v : NEG_SLOPE * v; }

template<int LAYER>
__global__ void __launch_bounds__(256) agg_kernel(
    const float* __restrict__ h,
    const float* __restrict__ ss,
    const float* __restrict__ sd,
    const float* __restrict__ bias,
    float* __restrict__ out,
    const float* __restrict__ xr,
    const float* __restrict__ br)
{
    __shared__ float2 pse[8][HEADS][CAP];   // per-head (src_as_float, exp_logit)

    int warp = (blockIdx.x * blockDim.x + threadIdx.x) >> 5;
    int wip  = threadIdx.x >> 5;
    int lane = threadIdx.x & 31;
    if (warp >= NN) return;
    int n = warp;
    int begin = g_offs[n], end = g_offs[n + 1];
    int deg = end - begin;

    float4 sdv = *(const float4*)&sd[n * HEADS];
    float4 ssn = *(const float4*)&ss[n * HEADS];
    // self-loop (softmax is shift-invariant; logits are O(1), exp never overflows)
    float es0 = __expf(lrelu(ssn.x + sdv.x));
    float es1 = __expf(lrelu(ssn.y + sdv.y));
    float es2 = __expf(lrelu(ssn.z + sdv.z));
    float es3 = __expf(lrelu(ssn.w + sdv.w));
    float d0 = 0.f, d1 = 0.f, d2 = 0.f, d3 = 0.f;

    int hd = lane >> 3;
    int c0 = lane * 4;

    if (deg <= CAP) {
        // single pass: gather scores -> exp logits into packed planes + denom
        for (int i = lane; i < deg; i += 32) {
            int s = g_sorted_src[begin + i];
            float4 sv = *(const float4*)&ss[s * HEADS];
            float fs = __int_as_float(s);
            float e0 = __expf(lrelu(sv.x + sdv.x));
            float e1 = __expf(lrelu(sv.y + sdv.y));
            float e2 = __expf(lrelu(sv.z + sdv.z));
            float e3 = __expf(lrelu(sv.w + sdv.w));
            pse[wip][0][i] = make_float2(fs, e0);
            pse[wip][1][i] = make_float2(fs, e1);
            pse[wip][2][i] = make_float2(fs, e2);
            pse[wip][3][i] = make_float2(fs, e3);
            d0 += e0; d1 += e1; d2 += e2; d3 += e3;
        }
#pragma unroll
        for (int off = 16; off; off >>= 1) {
            d0 += __shfl_xor_sync(0xffffffffu, d0, off);
            d1 += __shfl_xor_sync(0xffffffffu, d1, off);
            d2 += __shfl_xor_sync(0xffffffffu, d2, off);
            d3 += __shfl_xor_sync(0xffffffffu, d3, off);
        }
        d0 += es0; d1 += es1; d2 += es2; d3 += es3;
        __syncwarp();

        float dh  = (hd == 0) ? d0 : (hd == 1) ? d1 : (hd == 2) ? d2 : d3;
        float esh = (hd == 0) ? es0 : (hd == 1) ? es1 : (hd == 2) ? es2 : es3;
        float inv_dh = 1.f / dh;

        float4 hn = *(const float4*)&h[(long long)n * D + c0];
        float ax = esh * hn.x, ay = esh * hn.y, az = esh * hn.z, aw = esh * hn.w;

        const float2* __restrict__ pp = &pse[wip][hd][0];
#pragma unroll 4
        for (int i = 0; i < deg; ++i) {
            float2 p = pp[i];
            int s = __float_as_int(p.x);
            float e = p.y;
            float4 hv = *(const float4*)&h[(long long)s * D + c0];
            ax += e * hv.x; ay += e * hv.y; az += e * hv.z; aw += e * hv.w;
        }
        ax *= inv_dh; ay *= inv_dh; az *= inv_dh; aw *= inv_dh;

        float4 b = *(const float4*)&bias[c0];
        if (LAYER == 1) {
            float4 o = make_float4(fmaxf(ax + b.x, 0.f), fmaxf(ay + b.y, 0.f),
                                   fmaxf(az + b.z, 0.f), fmaxf(aw + b.w, 0.f));
            *(float4*)&out[(long long)n * D + c0] = o;
        } else {
            float4 r  = *(const float4*)&xr[(long long)n * D + c0];
            float4 bb = *(const float4*)&br[c0];
            float4 o = make_float4(ax + b.x + r.x + bb.x, ay + b.y + r.y + bb.y,
                                   az + b.z + r.z + bb.z, aw + b.w + r.w + bb.w);
            *(float4*)&out[(long long)n * D + c0] = o;
        }
        return;
    }

    // ---- fallback (deg > CAP; statistically unreachable) -------------------------
    for (int e = begin + lane; e < end; e += 32) {
        int s = g_sorted_src[e];
        float4 sv = *(const float4*)&ss[s * HEADS];
        d0 += __expf(lrelu(sv.x + sdv.x));
        d1 += __expf(lrelu(sv.y + sdv.y));
        d2 += __expf(lrelu(sv.z + sdv.z));
        d3 += __expf(lrelu(sv.w + sdv.w));
    }
#pragma unroll
    for (int off = 16; off; off >>= 1) {
        d0 += __shfl_xor_sync(0xffffffffu, d0, off);
        d1 += __shfl_xor_sync(0xffffffffu, d1, off);
        d2 += __shfl_xor_sync(0xffffffffu, d2, off);
        d3 += __shfl_xor_sync(0xffffffffu, d3, off);
    }
    d0 += es0; d1 += es1; d2 += es2; d3 += es3;

    float dh  = (hd == 0) ? d0 : (hd == 1) ? d1 : (hd == 2) ? d2 : d3;
    float esh = (hd == 0) ? es0 : (hd == 1) ? es1 : (hd == 2) ? es2 : es3;
    float sdh = (hd == 0) ? sdv.x : (hd == 1) ? sdv.y : (hd == 2) ? sdv.z : sdv.w;
    float inv_dh = 1.f / dh;

    float4 hn = *(const float4*)&h[(long long)n * D + c0];
    float ax = esh * hn.x, ay = esh * hn.y, az = esh * hn.z, aw = esh * hn.w;
    for (int e = begin; e < end; ++e) {
        int s = g_sorted_src[e];
        float w = __expf(lrelu(ss[s * HEADS + hd] + sdh));
        float4 hv = *(const float4*)&h[(long long)s * D + c0];
        ax += w * hv.x; ay += w * hv.y; az += w * hv.z; aw += w * hv.w;
    }
    ax *= inv_dh; ay *= inv_dh; az *= inv_dh; aw *= inv_dh;

    float4 b = *(const float4*)&bias[c0];
    if (LAYER == 1) {
        float4 o = make_float4(fmaxf(ax + b.x, 0.f), fmaxf(ay + b.y, 0.f),
                               fmaxf(az + b.z, 0.f), fmaxf(aw + b.w, 0.f));
        *(float4*)&out[(long long)n * D + c0] = o;
    } else {
        float4 r  = *(const float4*)&xr[(long long)n * D + c0];
        float4 bb = *(const float4*)&br[c0];
        float4 o = make_float4(ax + b.x + r.x + bb.x, ay + b.y + r.y + bb.y,
                               az + b.z + r.z + bb.z, aw + b.w + r.w + bb.w);
        *(float4*)&out[(long long)n * D + c0] = o;
    }
}

// ---------------- launch ----------------------------------------------------------
extern "C" void kernel_launch(void* const* d_in, const int* in_sizes, int n_in,
                              void* d_out, int out_size) {
    const float* x   = (const float*)d_in[0];
    const void*  ei  = d_in[1];
    const float* W1  = (const float*)d_in[2];
    const float* a1s = (const float*)d_in[3];
    const float* a1d = (const float*)d_in[4];
    const float* b1  = (const float*)d_in[5];
    const float* W2  = (const float*)d_in[6];
    const float* a2s = (const float*)d_in[7];
    const float* a2d = (const float*)d_in[8];
    const float* b2  = (const float*)d_in[9];
    const float* Wr  = (const float*)d_in[10];
    const float* br  = (const float*)d_in[11];
    float* out = (float*)d_out;

    float* bufA; cudaGetSymbolAddress((void**)&bufA, g_bufA);
    float* bufB; cudaGetSymbolAddress((void**)&bufB, g_bufB);
    float* xr;   cudaGetSymbolAddress((void**)&xr, g_xr);
    float* ssp;  cudaGetSymbolAddress((void**)&ssp, g_ss);
    float* sdp;  cudaGetSymbolAddress((void**)&sdp, g_sd);

    // 1: fused preprocessing (self-contained; zeroes its own state each launch)
    preproc_kernel<<<PP_BLOCKS, PP_THREADS>>>(ei);
    // 2: layer-1 transform + residual transform (reads x once)
    gemm_dual_kernel<<<(NN + 127) / 128, 512>>>(x, W1, Wr, a1s, a1d,
                                                bufA, xr, ssp, sdp);
    // 3: layer-1 aggregation
    agg_kernel<1><<<(NN + 7) / 8, 256>>>(bufA, ssp, sdp, b1, bufB, nullptr, nullptr);
    // 4: layer-2 transform + scores (profiled slot)
    gemm_tc_kernel<true><<<(NN + 127) / 128, 256>>>(bufB, W2, a2s, a2d, bufA, ssp, sdp);
    // 5: layer-2 aggregation + residual
    agg_kernel<2><<<(NN + 7) / 8, 256>>>(bufA, ssp, sdp, b2, out, xr, br);
}